// round 6
// baseline (speedup 1.0000x reference)
#include <cuda_runtime.h>

#define N_NODES 10000
#define N_EDGES 160000
#define TE 32                    // edges per block in the edge kernel

#define INV_SQRT_MUL 0.08838834764831845f   // 1/sqrt(128)
#define INV_SQRT3    0.57735026918962576f
#define OUT_SCALE    0.00390625f            // (1/sqrt(256)) / 16

typedef unsigned long long ull;

// ---------------------------------------------------------------------------
// Scratch (device globals: allocation-free)
// ---------------------------------------------------------------------------
__device__ float g_hps[N_NODES * 128];   // s_in @ (inv * W_scalar @ W1[0:128])
__device__ float g_hpr[N_NODES * 128];   // s_in @ (inv * W_scalar @ W1[128:256])
__device__ float g_su [N_NODES * 128];   // s_up
__device__ float g_vup[N_NODES * 384];   // v_up, layout [n][w][i] (i fastest)
__device__ float g_msg[N_NODES * 1024];  // segment-sum accumulator
__device__ float g_Wsa[128 * 128];       // inv * W_scalar @ W1[0:128]
__device__ float g_Wsb[128 * 128];       // inv * W_scalar @ W1[128:256]

static __device__ __forceinline__ float silu(float x) {
    return x / (1.0f + __expf(-x));
}

static __device__ __forceinline__ void red_add_v4(float* addr, float a, float b,
                                                  float c, float d) {
    asm volatile("red.global.add.v4.f32 [%0], {%1, %2, %3, %4};"
                 :: "l"(addr), "f"(a), "f"(b), "f"(c), "f"(d) : "memory");
}

// ---- packed f32x2 helpers --------------------------------------------------
static __device__ __forceinline__ ull pack2(float lo, float hi) {
    ull r; asm("mov.b64 %0, {%1, %2};" : "=l"(r) : "f"(lo), "f"(hi)); return r;
}
static __device__ __forceinline__ ull dup2(float x) {
    ull r; asm("mov.b64 %0, {%1, %1};" : "=l"(r) : "f"(x)); return r;
}
static __device__ __forceinline__ void fma2(ull& acc, ull a, ull b) {
    asm("fma.rn.f32x2 %0, %1, %2, %0;" : "+l"(acc) : "l"(a), "l"(b));
}
static __device__ __forceinline__ float2 unpack2(ull p) {
    float2 f; asm("mov.b64 {%0, %1}, %2;" : "=f"(f.x), "=f"(f.y) : "l"(p)); return f;
}

// ---------------------------------------------------------------------------
// Kernel 0: zero the message accumulator
// ---------------------------------------------------------------------------
__global__ void k_zero() {
    int i = blockIdx.x * blockDim.x + threadIdx.x;
    ((float4*)g_msg)[i] = make_float4(0.f, 0.f, 0.f, 0.f);
}

// ---------------------------------------------------------------------------
// Kernel W: fold W_scalar into the first MLP layer.
//   W_sa[u][w] = inv * sum_c Ws[u][c] * W1[c][w]        (sender rows)
//   W_sb[u][w] = inv * sum_c Ws[u][c] * W1[128+c][w]    (receiver rows)
// grid (128, 2), block 128.
// ---------------------------------------------------------------------------
__global__ void __launch_bounds__(128) k_w(
    const float* __restrict__ Ws, const float* __restrict__ W1)
{
    __shared__ float row[128];
    const int u = blockIdx.x, t = threadIdx.x;
    row[t] = Ws[u * 128 + t];
    __syncthreads();
    const float* W1p = W1 + (blockIdx.y ? 128 * 128 : 0);
    float a = 0.f;
#pragma unroll 4
    for (int c = 0; c < 128; ++c) a += row[c] * W1p[c * 128 + t];
    (blockIdx.y ? g_Wsb : g_Wsa)[u * 128 + t] = a * INV_SQRT_MUL;
}

// ---------------------------------------------------------------------------
// Kernel 1: per-node precompute, 4 nodes per block.
//   hp_s = s_in @ W_sa ; hp_r = s_in @ W_sb ; s_up = s_in @ W_up0 * inv
//   v_up[n,w,i] = sum_u v_in[n,u,i] * W_up1[u,w] * inv
// ---------------------------------------------------------------------------
__global__ void __launch_bounds__(128) k_node(
    const float* __restrict__ nf,
    const float* __restrict__ Wu0,
    const float* __restrict__ Wu1)
{
    __shared__ float s_sh[4][128];
    __shared__ float v_sh[4][384];
    const int n0 = blockIdx.x * 4;
    const int t = threadIdx.x;

#pragma unroll
    for (int nn = 0; nn < 4; ++nn) {
        const float* src = nf + (n0 + nn) * 512;
        s_sh[nn][t]       = src[t];
        v_sh[nn][t]       = src[128 + t];
        v_sh[nn][t + 128] = src[256 + t];
        v_sh[nn][t + 256] = src[384 + t];
    }
    __syncthreads();

    float as[4], ar[4], a1[4], av0[4], av1[4], av2[4];
#pragma unroll
    for (int nn = 0; nn < 4; ++nn) {
        as[nn]=0.f; ar[nn]=0.f; a1[nn]=0.f; av0[nn]=0.f; av1[nn]=0.f; av2[nn]=0.f;
    }

#pragma unroll 2
    for (int u = 0; u < 128; ++u) {
        float wsa = g_Wsa[u * 128 + t];
        float wsb = g_Wsb[u * 128 + t];
        float wu0 = Wu0[u * 128 + t];
        float wu1 = Wu1[u * 128 + t];
#pragma unroll
        for (int nn = 0; nn < 4; ++nn) {
            float s = s_sh[nn][u];
            as[nn] += s * wsa;
            ar[nn] += s * wsb;
            a1[nn] += s * wu0;
            av0[nn] += v_sh[nn][u * 3 + 0] * wu1;
            av1[nn] += v_sh[nn][u * 3 + 1] * wu1;
            av2[nn] += v_sh[nn][u * 3 + 2] * wu1;
        }
    }
#pragma unroll
    for (int nn = 0; nn < 4; ++nn) {
        int n = n0 + nn;
        g_hps[n * 128 + t] = as[nn];
        g_hpr[n * 128 + t] = ar[nn];
        g_su [n * 128 + t] = a1[nn] * INV_SQRT_MUL;
        g_vup[n * 384 + t * 3 + 0] = av0[nn] * INV_SQRT_MUL;
        g_vup[n * 384 + t * 3 + 1] = av1[nn] * INV_SQRT_MUL;
        g_vup[n * 384 + t * 3 + 2] = av2[nn] * INV_SQRT_MUL;
    }
}

// ---------------------------------------------------------------------------
// Kernel 2: per-edge MLP + message + scatter.
// Layer 1 is now: h1 = silu(b1 + hp_s[snd] + hp_r[rcv] + ef@W1[256:264] + len*W1[264])
// 128 threads, TE=32 edges. cg = t&31 -> cols c0=4cg..c0+3; warp owns 8 edges.
// ---------------------------------------------------------------------------
__global__ void __launch_bounds__(128, 4) k_edge(
    const float* __restrict__ edge_attrs,
    const float* __restrict__ edge_feats,
    const float* __restrict__ lengths,
    const int*   __restrict__ edge_index,
    const float* __restrict__ W1, const float* __restrict__ b1,
    const float* __restrict__ W2, const float* __restrict__ b2,
    const float* __restrict__ W3)
{
    __shared__ __align__(16) float x_sm[TE][272];
    // layout per edge row: [0:128) h1 then h2 stays at [128:256); [256:265) ef+len

    const int t  = threadIdx.x;
    const int cg = t & 31;
    const int c0 = cg * 4;
    const int e0 = (t >> 5) * 8;      // first of this thread's 8 edges
    const int ebase = blockIdx.x * TE;

    // ---- stage edge scalars: e = t>>2 (0..31), q = t&3 ----
    {
        const int e  = t >> 2;
        const int q  = t & 3;
        const int eg = ebase + e;
        if (q < 2) {
            *(float4*)&x_sm[e][256 + 4 * q] = ((const float4*)(edge_feats + eg * 8))[q];
        } else if (q == 2) {
            x_sm[e][264] = lengths[eg];
        }
    }
    __syncthreads();

    // ---- layer 1 (folded): tiny 9-row GEMM + gathered adds ----
    {
        float4 w1e[9];
#pragma unroll
        for (int r = 0; r < 9; ++r)
            w1e[r] = *(const float4*)(W1 + (256 + r) * 128 + c0);
        float4 bb = *(const float4*)(b1 + c0);

#pragma unroll
        for (int j = 0; j < 8; ++j) {
            const int eg  = ebase + e0 + j;
            const int snd = edge_index[eg];
            const int rcv = edge_index[N_EDGES + eg];
            float4 hs = *(const float4*)(g_hps + snd * 128 + c0);
            float4 hr = *(const float4*)(g_hpr + rcv * 128 + c0);
            float ef[9];
            {
                float4 q0 = *(const float4*)&x_sm[e0 + j][256];
                float4 q1 = *(const float4*)&x_sm[e0 + j][260];
                ef[0]=q0.x; ef[1]=q0.y; ef[2]=q0.z; ef[3]=q0.w;
                ef[4]=q1.x; ef[5]=q1.y; ef[6]=q1.z; ef[7]=q1.w;
                ef[8]=x_sm[e0 + j][264];
            }
            float a[4] = { bb.x + hs.x + hr.x, bb.y + hs.y + hr.y,
                           bb.z + hs.z + hr.z, bb.w + hs.w + hr.w };
#pragma unroll
            for (int r = 0; r < 9; ++r) {
                a[0] += ef[r] * w1e[r].x; a[1] += ef[r] * w1e[r].y;
                a[2] += ef[r] * w1e[r].z; a[3] += ef[r] * w1e[r].w;
            }
            *(float4*)&x_sm[e0 + j][c0] =
                make_float4(silu(a[0]), silu(a[1]), silu(a[2]), silu(a[3]));
        }
    }
    __syncthreads();

    // ---- layer 2: 128 -> 128, silu (f32x2) ----
    ull acc[8][2];
    {
        float4 b = *(const float4*)(b2 + c0);
        ull blo = pack2(b.x, b.y), bhi = pack2(b.z, b.w);
#pragma unroll
        for (int j = 0; j < 8; ++j) { acc[j][0] = blo; acc[j][1] = bhi; }

        for (int k = 0; k < 128; k += 4) {
            float4 xv[8];
#pragma unroll
            for (int j = 0; j < 8; ++j) xv[j] = *(const float4*)&x_sm[e0 + j][k];
#pragma unroll
            for (int kk = 0; kk < 4; ++kk) {
                ulonglong2 w = *(const ulonglong2*)(W2 + (k + kk) * 128 + c0);
#pragma unroll
                for (int j = 0; j < 8; ++j) {
                    float xs = (kk == 0) ? xv[j].x : (kk == 1) ? xv[j].y
                             : (kk == 2) ? xv[j].z : xv[j].w;
                    ull xd = dup2(xs);
                    fma2(acc[j][0], w.x, xd);
                    fma2(acc[j][1], w.y, xd);
                }
            }
        }
    }
    __syncthreads();                 // all reads of h1 done
#pragma unroll
    for (int j = 0; j < 8; ++j) {
        float2 lo = unpack2(acc[j][0]), hi = unpack2(acc[j][1]);
        *(float4*)&x_sm[e0 + j][128 + c0] =
            make_float4(silu(lo.x), silu(lo.y), silu(hi.x), silu(hi.y));
    }
    __syncthreads();
    // h2 lives in x_sm[e][128..255]

    // =======================================================================
    // layer 3 pass A: segments 0 (w0->m0a) and 1 (w1->m1a)
    // =======================================================================
    {
        ull pA[8][2], pB[8][2];
#pragma unroll
        for (int j = 0; j < 8; ++j) { pA[j][0]=0; pA[j][1]=0; pB[j][0]=0; pB[j][1]=0; }

        for (int k = 0; k < 128; k += 2) {
            float2 xv[8];
#pragma unroll
            for (int j = 0; j < 8; ++j) xv[j] = *(const float2*)&x_sm[e0 + j][128 + k];
#pragma unroll
            for (int kk = 0; kk < 2; ++kk) {
                const float* wr = W3 + (k + kk) * 512;
                ulonglong2 w0 = *(const ulonglong2*)(wr + c0);
                ulonglong2 w1 = *(const ulonglong2*)(wr + 128 + c0);
#pragma unroll
                for (int j = 0; j < 8; ++j) {
                    ull xd = dup2(kk ? xv[j].y : xv[j].x);
                    fma2(pA[j][0], w0.x, xd); fma2(pA[j][1], w0.y, xd);
                    fma2(pB[j][0], w1.x, xd); fma2(pB[j][1], w1.y, xd);
                }
            }
        }

        // scatter m0a (cols [0,128)) and m1a (cols [256,640))
#pragma unroll
        for (int j = 0; j < 8; ++j) {
            const int eg  = ebase + e0 + j;
            const int snd = edge_index[eg];
            const int rcv = edge_index[N_EDGES + eg];
            float4 ea  = *(const float4*)(edge_attrs + eg * 4);
            float4 sev = *(const float4*)(g_su + snd * 128 + c0);
            const float y0 = ea.x, y1x = ea.y, y1y = ea.z, y1z = ea.w;
            float2 l0 = unpack2(pA[j][0]), h0 = unpack2(pA[j][1]);
            float2 l1 = unpack2(pB[j][0]), h1 = unpack2(pB[j][1]);
            const float a0v[4] = {l0.x, l0.y, h0.x, h0.y};
            const float a1v[4] = {l1.x, l1.y, h1.x, h1.y};
            const float se[4]  = {sev.x, sev.y, sev.z, sev.w};

            float* base = g_msg + rcv * 1024;
            red_add_v4(base + c0,
                       a0v[0]*se[0]*y0, a0v[1]*se[1]*y0,
                       a0v[2]*se[2]*y0, a0v[3]*se[3]*y0);

            float o[12];
#pragma unroll
            for (int m = 0; m < 4; ++m) {
                float t1 = a1v[m] * se[m];
                o[3*m+0] = t1 * y1x; o[3*m+1] = t1 * y1y; o[3*m+2] = t1 * y1z;
            }
            float* p = base + 256 + c0 * 3;
            red_add_v4(p,     o[0], o[1], o[2],  o[3]);
            red_add_v4(p + 4, o[4], o[5], o[6],  o[7]);
            red_add_v4(p + 8, o[8], o[9], o[10], o[11]);
        }
    }

    // =======================================================================
    // layer 3 pass B: segments 2 (w2->m1b) and 3 (w3->m0b)
    // =======================================================================
    {
        ull pA[8][2], pB[8][2];
#pragma unroll
        for (int j = 0; j < 8; ++j) { pA[j][0]=0; pA[j][1]=0; pB[j][0]=0; pB[j][1]=0; }

        for (int k = 0; k < 128; k += 2) {
            float2 xv[8];
#pragma unroll
            for (int j = 0; j < 8; ++j) xv[j] = *(const float2*)&x_sm[e0 + j][128 + k];
#pragma unroll
            for (int kk = 0; kk < 2; ++kk) {
                const float* wr = W3 + (k + kk) * 512;
                ulonglong2 w2 = *(const ulonglong2*)(wr + 256 + c0);
                ulonglong2 w3 = *(const ulonglong2*)(wr + 384 + c0);
#pragma unroll
                for (int j = 0; j < 8; ++j) {
                    ull xd = dup2(kk ? xv[j].y : xv[j].x);
                    fma2(pA[j][0], w2.x, xd); fma2(pA[j][1], w2.y, xd);
                    fma2(pB[j][0], w3.x, xd); fma2(pB[j][1], w3.y, xd);
                }
            }
        }

        // scatter m1b (cols [640,1024)) and m0b (cols [128,256))
#pragma unroll
        for (int j = 0; j < 8; ++j) {
            const int eg  = ebase + e0 + j;
            const int snd = edge_index[eg];
            const int rcv = edge_index[N_EDGES + eg];
            float4 ea = *(const float4*)(edge_attrs + eg * 4);
            const float y0 = ea.x, y1x = ea.y, y1y = ea.z, y1z = ea.w;

            float f[12];
            {
                const float4* pv = (const float4*)(g_vup + snd * 384 + c0 * 3);
                float4 v0 = pv[0], v1 = pv[1], v2 = pv[2];
                f[0]=v0.x; f[1]=v0.y; f[2]=v0.z;  f[3]=v0.w;
                f[4]=v1.x; f[5]=v1.y; f[6]=v1.z;  f[7]=v1.w;
                f[8]=v2.x; f[9]=v2.y; f[10]=v2.z; f[11]=v2.w;
            }
            float2 l2 = unpack2(pA[j][0]), h2 = unpack2(pA[j][1]);
            float2 l3 = unpack2(pB[j][0]), h3 = unpack2(pB[j][1]);
            const float a2v[4] = {l2.x, l2.y, h2.x, h2.y};
            const float a3v[4] = {l3.x, l3.y, h3.x, h3.y};

            float* base = g_msg + rcv * 1024;

            {   // m0b
                float m[4];
#pragma unroll
                for (int mc = 0; mc < 4; ++mc) {
                    float dot = f[3*mc]*y1x + f[3*mc+1]*y1y + f[3*mc+2]*y1z;
                    m[mc] = a3v[mc] * dot * INV_SQRT3;
                }
                red_add_v4(base + 128 + c0, m[0], m[1], m[2], m[3]);
            }
            {   // m1b
                float o[12];
#pragma unroll
                for (int mc = 0; mc < 4; ++mc) {
                    float t2 = a2v[mc] * y0;
                    o[3*mc+0] = t2 * f[3*mc+0];
                    o[3*mc+1] = t2 * f[3*mc+1];
                    o[3*mc+2] = t2 * f[3*mc+2];
                }
                float* p = base + 640 + c0 * 3;
                red_add_v4(p,     o[0], o[1], o[2],  o[3]);
                red_add_v4(p + 4, o[4], o[5], o[6],  o[7]);
                red_add_v4(p + 8, o[8], o[9], o[10], o[11]);
            }
        }
    }
}

// ---------------------------------------------------------------------------
// Kernel 3: node output. 8 nodes per block, 256 threads:
// tc = t&127 is the output column, half = t>>7 selects node group (4 nodes).
// ---------------------------------------------------------------------------
__global__ void __launch_bounds__(256) k_out(
    const float* __restrict__ W0,
    const float* __restrict__ W1o,
    float* __restrict__ out)
{
    __shared__ __align__(16) float m_sm[8 * 1024];
    const int n0 = blockIdx.x * 8;
    const int t  = threadIdx.x;
    const int tc = t & 127;
    const int nb = (t >> 7) * 4;      // node group base: 0 or 4

    {
        const float4* src = (const float4*)(g_msg + n0 * 1024);
        float4* dst = (float4*)m_sm;
#pragma unroll
        for (int i = 0; i < 8; ++i) dst[t + 256 * i] = src[t + 256 * i];
    }
    __syncthreads();

    float a0[4], v0[4], v1[4], v2[4];
#pragma unroll
    for (int nn = 0; nn < 4; ++nn) { a0[nn]=0.f; v0[nn]=0.f; v1[nn]=0.f; v2[nn]=0.f; }

    for (int u = 0; u < 256; u += 4) {
        float w0[4], w1[4];
#pragma unroll
        for (int i = 0; i < 4; ++i) {
            w0[i] = W0 [(u + i) * 128 + tc];
            w1[i] = W1o[(u + i) * 128 + tc];
        }
#pragma unroll
        for (int nn = 0; nn < 4; ++nn) {
            const float* row = m_sm + (nb + nn) * 1024;
            float4 ms = *(const float4*)&row[u];
            a0[nn] += ms.x * w0[0] + ms.y * w0[1] + ms.z * w0[2] + ms.w * w0[3];
            float4 va = *(const float4*)&row[256 + u * 3];
            float4 vb = *(const float4*)&row[256 + u * 3 + 4];
            float4 vc = *(const float4*)&row[256 + u * 3 + 8];
            // u+0: (va.x va.y va.z)  u+1: (va.w vb.x vb.y)
            // u+2: (vb.z vb.w vc.x)  u+3: (vc.y vc.z vc.w)
            v0[nn] += va.x * w1[0] + va.w * w1[1] + vb.z * w1[2] + vc.y * w1[3];
            v1[nn] += va.y * w1[0] + vb.x * w1[1] + vb.w * w1[2] + vc.z * w1[3];
            v2[nn] += va.z * w1[0] + vb.y * w1[1] + vc.x * w1[2] + vc.w * w1[3];
        }
    }

#pragma unroll
    for (int nn = 0; nn < 4; ++nn) {
        *(float4*)(out + (n0 + nb + nn) * 512 + tc * 4) =
            make_float4(a0[nn] * OUT_SCALE, v0[nn] * OUT_SCALE,
                        v1[nn] * OUT_SCALE, v2[nn] * OUT_SCALE);
    }
}

// ---------------------------------------------------------------------------
// Launch
// ---------------------------------------------------------------------------
extern "C" void kernel_launch(void* const* d_in, const int* in_sizes, int n_in,
                              void* d_out, int out_size)
{
    const float* node_feats = (const float*)d_in[0];
    const float* edge_attrs = (const float*)d_in[1];
    const float* edge_feats = (const float*)d_in[2];
    const float* lengths    = (const float*)d_in[3];
    const int*   edge_index = (const int*)  d_in[4];
    const float* W_scalar   = (const float*)d_in[5];
    const float* W_up0      = (const float*)d_in[6];
    const float* W_up1      = (const float*)d_in[7];
    const float* W_mlp1     = (const float*)d_in[8];
    const float* b_mlp1     = (const float*)d_in[9];
    const float* W_mlp2     = (const float*)d_in[10];
    const float* b_mlp2     = (const float*)d_in[11];
    const float* W_mlp3     = (const float*)d_in[12];
    const float* W_out0     = (const float*)d_in[13];
    const float* W_out1     = (const float*)d_in[14];
    float* out = (float*)d_out;

    k_zero<<<5000, 512>>>();
    k_w<<<dim3(128, 2), 128>>>(W_scalar, W_mlp1);
    k_node<<<N_NODES / 4, 128>>>(node_feats, W_up0, W_up1);
    k_edge<<<N_EDGES / TE, 128>>>(edge_attrs, edge_feats, lengths, edge_index,
                                  W_mlp1, b_mlp1, W_mlp2, b_mlp2, W_mlp3);
    k_out<<<N_NODES / 8, 256>>>(W_out0, W_out1, out);
}

// round 7
// speedup vs baseline: 1.2013x; 1.2013x over previous
#include <cuda_runtime.h>

#define N_NODES 10000
#define N_EDGES 160000
#define TE 32                    // edges per block in the edge kernel

#define INV_SQRT_MUL 0.08838834764831845f   // 1/sqrt(128)
#define INV_SQRT3    0.57735026918962576f
#define OUT_SCALE    0.00390625f            // (1/sqrt(256)) / 16

typedef unsigned long long ull;

// ---------------------------------------------------------------------------
// Scratch (device globals: allocation-free)
// ---------------------------------------------------------------------------
__device__ float g_hps[N_NODES * 128];   // s_in @ (inv * W_scalar @ W1[0:128])
__device__ float g_hpr[N_NODES * 128];   // s_in @ (inv * W_scalar @ W1[128:256])
__device__ float g_su [N_NODES * 128];   // s_up
__device__ float g_vup[N_NODES * 384];   // v_up, layout [n][w][i] (i fastest)
__device__ float g_msg[N_NODES * 1024];  // segment-sum accumulator
__device__ float g_Wsa[128 * 128];       // inv * W_scalar @ W1[0:128]
__device__ float g_Wsb[128 * 128];       // inv * W_scalar @ W1[128:256]

static __device__ __forceinline__ float silu(float x) {
    return x / (1.0f + __expf(-x));
}

static __device__ __forceinline__ void red_add_v4(float* addr, float a, float b,
                                                  float c, float d) {
    asm volatile("red.global.add.v4.f32 [%0], {%1, %2, %3, %4};"
                 :: "l"(addr), "f"(a), "f"(b), "f"(c), "f"(d) : "memory");
}

// ---- packed f32x2 helpers --------------------------------------------------
static __device__ __forceinline__ ull pack2(float lo, float hi) {
    ull r; asm("mov.b64 %0, {%1, %2};" : "=l"(r) : "f"(lo), "f"(hi)); return r;
}
static __device__ __forceinline__ ull dup2(float x) {
    ull r; asm("mov.b64 %0, {%1, %1};" : "=l"(r) : "f"(x)); return r;
}
static __device__ __forceinline__ void fma2(ull& acc, ull a, ull b) {
    asm("fma.rn.f32x2 %0, %1, %2, %0;" : "+l"(acc) : "l"(a), "l"(b));
}
static __device__ __forceinline__ float2 unpack2(ull p) {
    float2 f; asm("mov.b64 {%0, %1}, %2;" : "=f"(f.x), "=f"(f.y) : "l"(p)); return f;
}

// ---------------------------------------------------------------------------
// Kernel 0: zero the message accumulator
// ---------------------------------------------------------------------------
__global__ void k_zero() {
    int i = blockIdx.x * blockDim.x + threadIdx.x;
    ((float4*)g_msg)[i] = make_float4(0.f, 0.f, 0.f, 0.f);
}

// ---------------------------------------------------------------------------
// Kernel W: fold W_scalar into the first MLP layer.
// ---------------------------------------------------------------------------
__global__ void __launch_bounds__(128) k_w(
    const float* __restrict__ Ws, const float* __restrict__ W1)
{
    __shared__ float row[128];
    const int u = blockIdx.x, t = threadIdx.x;
    row[t] = Ws[u * 128 + t];
    __syncthreads();
    const float* W1p = W1 + (blockIdx.y ? 128 * 128 : 0);
    float a = 0.f;
#pragma unroll 4
    for (int c = 0; c < 128; ++c) a += row[c] * W1p[c * 128 + t];
    (blockIdx.y ? g_Wsb : g_Wsa)[u * 128 + t] = a * INV_SQRT_MUL;
}

// ---------------------------------------------------------------------------
// Kernel 1: per-node precompute, 4 nodes per block.
// ---------------------------------------------------------------------------
__global__ void __launch_bounds__(128) k_node(
    const float* __restrict__ nf,
    const float* __restrict__ Wu0,
    const float* __restrict__ Wu1)
{
    __shared__ float s_sh[4][128];
    __shared__ float v_sh[4][384];
    const int n0 = blockIdx.x * 4;
    const int t = threadIdx.x;

#pragma unroll
    for (int nn = 0; nn < 4; ++nn) {
        const float* src = nf + (n0 + nn) * 512;
        s_sh[nn][t]       = src[t];
        v_sh[nn][t]       = src[128 + t];
        v_sh[nn][t + 128] = src[256 + t];
        v_sh[nn][t + 256] = src[384 + t];
    }
    __syncthreads();

    float as[4], ar[4], a1[4], av0[4], av1[4], av2[4];
#pragma unroll
    for (int nn = 0; nn < 4; ++nn) {
        as[nn]=0.f; ar[nn]=0.f; a1[nn]=0.f; av0[nn]=0.f; av1[nn]=0.f; av2[nn]=0.f;
    }

#pragma unroll 2
    for (int u = 0; u < 128; ++u) {
        float wsa = g_Wsa[u * 128 + t];
        float wsb = g_Wsb[u * 128 + t];
        float wu0 = Wu0[u * 128 + t];
        float wu1 = Wu1[u * 128 + t];
#pragma unroll
        for (int nn = 0; nn < 4; ++nn) {
            float s = s_sh[nn][u];
            as[nn] += s * wsa;
            ar[nn] += s * wsb;
            a1[nn] += s * wu0;
            av0[nn] += v_sh[nn][u * 3 + 0] * wu1;
            av1[nn] += v_sh[nn][u * 3 + 1] * wu1;
            av2[nn] += v_sh[nn][u * 3 + 2] * wu1;
        }
    }
#pragma unroll
    for (int nn = 0; nn < 4; ++nn) {
        int n = n0 + nn;
        g_hps[n * 128 + t] = as[nn];
        g_hpr[n * 128 + t] = ar[nn];
        g_su [n * 128 + t] = a1[nn] * INV_SQRT_MUL;
        g_vup[n * 384 + t * 3 + 0] = av0[nn] * INV_SQRT_MUL;
        g_vup[n * 384 + t * 3 + 1] = av1[nn] * INV_SQRT_MUL;
        g_vup[n * 384 + t * 3 + 2] = av2[nn] * INV_SQRT_MUL;
    }
}

// ---------------------------------------------------------------------------
// Kernel 2: per-edge MLP + message + scatter. f32x2 packed FMA.
// 128 threads, TE=32. cg=t&31 -> cols c0=4cg..c0+3; warp owns 8 edges.
// Layer 3 = 4 single-segment k-sweeps, each fused with its scatter
// (outputs disjoint), keeping live accumulators at 16 packs -> low regs,
// 6 blocks/SM for latency hiding.
// ---------------------------------------------------------------------------
__global__ void __launch_bounds__(128, 6) k_edge(
    const float* __restrict__ edge_attrs,
    const float* __restrict__ edge_feats,
    const float* __restrict__ lengths,
    const int*   __restrict__ edge_index,
    const float* __restrict__ W1, const float* __restrict__ b1,
    const float* __restrict__ W2, const float* __restrict__ b2,
    const float* __restrict__ W3)
{
    __shared__ __align__(16) float x_sm[TE][272];
    // per edge row: [0:128) h1; [128:256) h2; [256:265) ef+len

    const int t  = threadIdx.x;
    const int cg = t & 31;
    const int c0 = cg * 4;
    const int e0 = (t >> 5) * 8;      // first of this thread's 8 edges
    const int ebase = blockIdx.x * TE;

    // ---- stage edge scalars: e = t>>2 (0..31), q = t&3 ----
    {
        const int e  = t >> 2;
        const int q  = t & 3;
        const int eg = ebase + e;
        if (q < 2) {
            *(float4*)&x_sm[e][256 + 4 * q] = ((const float4*)(edge_feats + eg * 8))[q];
        } else if (q == 2) {
            x_sm[e][264] = lengths[eg];
        }
    }
    __syncthreads();

    // ---- layer 1 (folded): tiny 9-row GEMM + gathered adds ----
    {
        float4 bb = *(const float4*)(b1 + c0);
#pragma unroll
        for (int j = 0; j < 8; ++j) {
            const int eg  = ebase + e0 + j;
            const int snd = edge_index[eg];
            const int rcv = edge_index[N_EDGES + eg];
            float4 hs = *(const float4*)(g_hps + snd * 128 + c0);
            float4 hr = *(const float4*)(g_hpr + rcv * 128 + c0);
            float a[4] = { bb.x + hs.x + hr.x, bb.y + hs.y + hr.y,
                           bb.z + hs.z + hr.z, bb.w + hs.w + hr.w };
#pragma unroll
            for (int r = 0; r < 9; ++r) {
                float efr = x_sm[e0 + j][256 + r];
                float4 w = *(const float4*)(W1 + (256 + r) * 128 + c0);
                a[0] += efr * w.x; a[1] += efr * w.y;
                a[2] += efr * w.z; a[3] += efr * w.w;
            }
            *(float4*)&x_sm[e0 + j][c0] =
                make_float4(silu(a[0]), silu(a[1]), silu(a[2]), silu(a[3]));
        }
    }
    __syncthreads();

    // ---- layer 2: 128 -> 128, silu (f32x2), k step 2 ----
    {
        ull acc[8][2];
        float4 b = *(const float4*)(b2 + c0);
        ull blo = pack2(b.x, b.y), bhi = pack2(b.z, b.w);
#pragma unroll
        for (int j = 0; j < 8; ++j) { acc[j][0] = blo; acc[j][1] = bhi; }

        for (int k = 0; k < 128; k += 2) {
            float2 xv[8];
#pragma unroll
            for (int j = 0; j < 8; ++j) xv[j] = *(const float2*)&x_sm[e0 + j][k];
#pragma unroll
            for (int kk = 0; kk < 2; ++kk) {
                ulonglong2 w = *(const ulonglong2*)(W2 + (k + kk) * 128 + c0);
#pragma unroll
                for (int j = 0; j < 8; ++j) {
                    ull xd = dup2(kk ? xv[j].y : xv[j].x);
                    fma2(acc[j][0], w.x, xd);
                    fma2(acc[j][1], w.y, xd);
                }
            }
        }
        __syncthreads();             // all reads of h1 done
#pragma unroll
        for (int j = 0; j < 8; ++j) {
            float2 lo = unpack2(acc[j][0]), hi = unpack2(acc[j][1]);
            *(float4*)&x_sm[e0 + j][128 + c0] =
                make_float4(silu(lo.x), silu(lo.y), silu(hi.x), silu(hi.y));
        }
    }
    __syncthreads();
    // h2 in x_sm[e][128..256), read-only from here on.

    // ======== layer 3: four single-segment sweeps, fused scatter ==========
#pragma unroll 1
    for (int seg = 0; seg < 4; ++seg) {
        ull acc[8][2];
#pragma unroll
        for (int j = 0; j < 8; ++j) { acc[j][0] = 0; acc[j][1] = 0; }

        const float* Wseg = W3 + seg * 128 + c0;
        for (int k = 0; k < 128; k += 2) {
            float2 xv[8];
#pragma unroll
            for (int j = 0; j < 8; ++j) xv[j] = *(const float2*)&x_sm[e0 + j][128 + k];
#pragma unroll
            for (int kk = 0; kk < 2; ++kk) {
                ulonglong2 w = *(const ulonglong2*)(Wseg + (k + kk) * 512);
#pragma unroll
                for (int j = 0; j < 8; ++j) {
                    ull xd = dup2(kk ? xv[j].y : xv[j].x);
                    fma2(acc[j][0], w.x, xd);
                    fma2(acc[j][1], w.y, xd);
                }
            }
        }

        // ---- fused scatter for this segment ----
#pragma unroll
        for (int j = 0; j < 8; ++j) {
            const int eg  = ebase + e0 + j;
            const int snd = edge_index[eg];
            const int rcv = edge_index[N_EDGES + eg];
            float4 ea = *(const float4*)(edge_attrs + eg * 4);
            float2 lo = unpack2(acc[j][0]), hi = unpack2(acc[j][1]);
            const float av[4] = {lo.x, lo.y, hi.x, hi.y};
            float* base = g_msg + rcv * 1024;

            if (seg == 0) {          // m0a = w0*se*y0 -> [0,128)
                float4 sev = *(const float4*)(g_su + snd * 128 + c0);
                red_add_v4(base + c0,
                           av[0]*sev.x*ea.x, av[1]*sev.y*ea.x,
                           av[2]*sev.z*ea.x, av[3]*sev.w*ea.x);
            } else if (seg == 1) {   // m1a = (w1*se) (x) y1 -> [256,640)
                float4 sev = *(const float4*)(g_su + snd * 128 + c0);
                const float se[4] = {sev.x, sev.y, sev.z, sev.w};
                float o[12];
#pragma unroll
                for (int m = 0; m < 4; ++m) {
                    float t1 = av[m] * se[m];
                    o[3*m+0] = t1 * ea.y; o[3*m+1] = t1 * ea.z; o[3*m+2] = t1 * ea.w;
                }
                float* p = base + 256 + c0 * 3;
                red_add_v4(p,     o[0], o[1], o[2],  o[3]);
                red_add_v4(p + 4, o[4], o[5], o[6],  o[7]);
                red_add_v4(p + 8, o[8], o[9], o[10], o[11]);
            } else if (seg == 2) {   // m1b = (w2*y0) * ve -> [640,1024)
                const float4* pv = (const float4*)(g_vup + snd * 384 + c0 * 3);
                float4 v0 = pv[0], v1 = pv[1], v2 = pv[2];
                float o[12];
                o[0]  = av[0]*ea.x*v0.x; o[1]  = av[0]*ea.x*v0.y; o[2]  = av[0]*ea.x*v0.z;
                o[3]  = av[1]*ea.x*v0.w; o[4]  = av[1]*ea.x*v1.x; o[5]  = av[1]*ea.x*v1.y;
                o[6]  = av[2]*ea.x*v1.z; o[7]  = av[2]*ea.x*v1.w; o[8]  = av[2]*ea.x*v2.x;
                o[9]  = av[3]*ea.x*v2.y; o[10] = av[3]*ea.x*v2.z; o[11] = av[3]*ea.x*v2.w;
                float* p = base + 640 + c0 * 3;
                red_add_v4(p,     o[0], o[1], o[2],  o[3]);
                red_add_v4(p + 4, o[4], o[5], o[6],  o[7]);
                red_add_v4(p + 8, o[8], o[9], o[10], o[11]);
            } else {                 // m0b = w3*(ve.y1)*inv_sqrt3 -> [128,256)
                const float4* pv = (const float4*)(g_vup + snd * 384 + c0 * 3);
                float4 v0 = pv[0], v1 = pv[1], v2 = pv[2];
                float d0 = v0.x*ea.y + v0.y*ea.z + v0.z*ea.w;
                float d1 = v0.w*ea.y + v1.x*ea.z + v1.y*ea.w;
                float d2 = v1.z*ea.y + v1.w*ea.z + v2.x*ea.w;
                float d3 = v2.y*ea.y + v2.z*ea.z + v2.w*ea.w;
                red_add_v4(base + 128 + c0,
                           av[0]*d0*INV_SQRT3, av[1]*d1*INV_SQRT3,
                           av[2]*d2*INV_SQRT3, av[3]*d3*INV_SQRT3);
            }
        }
    }
}

// ---------------------------------------------------------------------------
// Kernel 3: node output. 8 nodes per block, 256 threads.
// ---------------------------------------------------------------------------
__global__ void __launch_bounds__(256) k_out(
    const float* __restrict__ W0,
    const float* __restrict__ W1o,
    float* __restrict__ out)
{
    __shared__ __align__(16) float m_sm[8 * 1024];
    const int n0 = blockIdx.x * 8;
    const int t  = threadIdx.x;
    const int tc = t & 127;
    const int nb = (t >> 7) * 4;      // node group base: 0 or 4

    {
        const float4* src = (const float4*)(g_msg + n0 * 1024);
        float4* dst = (float4*)m_sm;
#pragma unroll
        for (int i = 0; i < 8; ++i) dst[t + 256 * i] = src[t + 256 * i];
    }
    __syncthreads();

    float a0[4], v0[4], v1[4], v2[4];
#pragma unroll
    for (int nn = 0; nn < 4; ++nn) { a0[nn]=0.f; v0[nn]=0.f; v1[nn]=0.f; v2[nn]=0.f; }

    for (int u = 0; u < 256; u += 4) {
        float w0[4], w1[4];
#pragma unroll
        for (int i = 0; i < 4; ++i) {
            w0[i] = W0 [(u + i) * 128 + tc];
            w1[i] = W1o[(u + i) * 128 + tc];
        }
#pragma unroll
        for (int nn = 0; nn < 4; ++nn) {
            const float* row = m_sm + (nb + nn) * 1024;
            float4 ms = *(const float4*)&row[u];
            a0[nn] += ms.x * w0[0] + ms.y * w0[1] + ms.z * w0[2] + ms.w * w0[3];
            float4 va = *(const float4*)&row[256 + u * 3];
            float4 vb = *(const float4*)&row[256 + u * 3 + 4];
            float4 vc = *(const float4*)&row[256 + u * 3 + 8];
            v0[nn] += va.x * w1[0] + va.w * w1[1] + vb.z * w1[2] + vc.y * w1[3];
            v1[nn] += va.y * w1[0] + vb.x * w1[1] + vb.w * w1[2] + vc.z * w1[3];
            v2[nn] += va.z * w1[0] + vb.y * w1[1] + vc.x * w1[2] + vc.w * w1[3];
        }
    }

#pragma unroll
    for (int nn = 0; nn < 4; ++nn) {
        *(float4*)(out + (n0 + nb + nn) * 512 + tc * 4) =
            make_float4(a0[nn] * OUT_SCALE, v0[nn] * OUT_SCALE,
                        v1[nn] * OUT_SCALE, v2[nn] * OUT_SCALE);
    }
}

// ---------------------------------------------------------------------------
// Launch
// ---------------------------------------------------------------------------
extern "C" void kernel_launch(void* const* d_in, const int* in_sizes, int n_in,
                              void* d_out, int out_size)
{
    const float* node_feats = (const float*)d_in[0];
    const float* edge_attrs = (const float*)d_in[1];
    const float* edge_feats = (const float*)d_in[2];
    const float* lengths    = (const float*)d_in[3];
    const int*   edge_index = (const int*)  d_in[4];
    const float* W_scalar   = (const float*)d_in[5];
    const float* W_up0      = (const float*)d_in[6];
    const float* W_up1      = (const float*)d_in[7];
    const float* W_mlp1     = (const float*)d_in[8];
    const float* b_mlp1     = (const float*)d_in[9];
    const float* W_mlp2     = (const float*)d_in[10];
    const float* b_mlp2     = (const float*)d_in[11];
    const float* W_mlp3     = (const float*)d_in[12];
    const float* W_out0     = (const float*)d_in[13];
    const float* W_out1     = (const float*)d_in[14];
    float* out = (float*)d_out;

    k_zero<<<5000, 512>>>();
    k_w<<<dim3(128, 2), 128>>>(W_scalar, W_mlp1);
    k_node<<<N_NODES / 4, 128>>>(node_feats, W_up0, W_up1);
    k_edge<<<N_EDGES / TE, 128>>>(edge_attrs, edge_feats, lengths, edge_index,
                                  W_mlp1, b_mlp1, W_mlp2, b_mlp2, W_mlp3);
    k_out<<<N_NODES / 8, 256>>>(W_out0, W_out1, out);
}

// round 8
// speedup vs baseline: 1.2034x; 1.0017x over previous
#include <cuda_runtime.h>

#define N_NODES 10000
#define N_EDGES 160000
#define TE 32                    // edges per block in the edge kernel

#define INV_SQRT_MUL 0.08838834764831845f   // 1/sqrt(128)
#define INV_SQRT3    0.57735026918962576f
#define OUT_SCALE    0.00390625f            // (1/sqrt(256)) / 16

typedef unsigned long long ull;

// ---------------------------------------------------------------------------
// Scratch (device globals: allocation-free)
// ---------------------------------------------------------------------------
__device__ float g_hps[N_NODES * 128];   // s_in @ (inv * W_scalar @ W1[0:128])
__device__ float g_hpr[N_NODES * 128];   // s_in @ (inv * W_scalar @ W1[128:256])
__device__ float g_su [N_NODES * 128];   // s_up
__device__ float g_vup[N_NODES * 384];   // v_up, layout [n][w][i] (i fastest)
__device__ float g_msg[N_NODES * 1024];  // segment-sum accumulator
__device__ float g_Wsa[128 * 128];       // inv * W_scalar @ W1[0:128]
__device__ float g_Wsb[128 * 128];       // inv * W_scalar @ W1[128:256]

static __device__ __forceinline__ float silu(float x) {
    return x / (1.0f + __expf(-x));
}

static __device__ __forceinline__ void red_add_v4(float* addr, float a, float b,
                                                  float c, float d) {
    asm volatile("red.global.add.v4.f32 [%0], {%1, %2, %3, %4};"
                 :: "l"(addr), "f"(a), "f"(b), "f"(c), "f"(d) : "memory");
}

// ---- packed f32x2 helpers --------------------------------------------------
static __device__ __forceinline__ ull dup2(float x) {
    ull r; asm("mov.b64 %0, {%1, %1};" : "=l"(r) : "f"(x)); return r;
}
static __device__ __forceinline__ void fma2(ull& acc, ull a, ull b) {
    asm("fma.rn.f32x2 %0, %1, %2, %0;" : "+l"(acc) : "l"(a), "l"(b));
}
static __device__ __forceinline__ float2 unpack2(ull p) {
    float2 f; asm("mov.b64 {%0, %1}, %2;" : "=f"(f.x), "=f"(f.y) : "l"(p)); return f;
}

// ---------------------------------------------------------------------------
// Kernel 0: zero the message accumulator
// ---------------------------------------------------------------------------
__global__ void k_zero() {
    int i = blockIdx.x * blockDim.x + threadIdx.x;
    ((float4*)g_msg)[i] = make_float4(0.f, 0.f, 0.f, 0.f);
}

// ---------------------------------------------------------------------------
// Kernel W: fold W_scalar into the first MLP layer.
// ---------------------------------------------------------------------------
__global__ void __launch_bounds__(128) k_w(
    const float* __restrict__ Ws, const float* __restrict__ W1)
{
    __shared__ float row[128];
    const int u = blockIdx.x, t = threadIdx.x;
    row[t] = Ws[u * 128 + t];
    __syncthreads();
    const float* W1p = W1 + (blockIdx.y ? 128 * 128 : 0);
    float a = 0.f;
#pragma unroll 4
    for (int c = 0; c < 128; ++c) a += row[c] * W1p[c * 128 + t];
    (blockIdx.y ? g_Wsb : g_Wsa)[u * 128 + t] = a * INV_SQRT_MUL;
}

// ---------------------------------------------------------------------------
// Kernel 1: per-node precompute, 4 nodes per block.
// ---------------------------------------------------------------------------
__global__ void __launch_bounds__(128) k_node(
    const float* __restrict__ nf,
    const float* __restrict__ Wu0,
    const float* __restrict__ Wu1)
{
    __shared__ float s_sh[4][128];
    __shared__ float v_sh[4][384];
    const int n0 = blockIdx.x * 4;
    const int t = threadIdx.x;

#pragma unroll
    for (int nn = 0; nn < 4; ++nn) {
        const float* src = nf + (n0 + nn) * 512;
        s_sh[nn][t]       = src[t];
        v_sh[nn][t]       = src[128 + t];
        v_sh[nn][t + 128] = src[256 + t];
        v_sh[nn][t + 256] = src[384 + t];
    }
    __syncthreads();

    float as[4], ar[4], a1[4], av0[4], av1[4], av2[4];
#pragma unroll
    for (int nn = 0; nn < 4; ++nn) {
        as[nn]=0.f; ar[nn]=0.f; a1[nn]=0.f; av0[nn]=0.f; av1[nn]=0.f; av2[nn]=0.f;
    }

#pragma unroll 2
    for (int u = 0; u < 128; ++u) {
        float wsa = g_Wsa[u * 128 + t];
        float wsb = g_Wsb[u * 128 + t];
        float wu0 = Wu0[u * 128 + t];
        float wu1 = Wu1[u * 128 + t];
#pragma unroll
        for (int nn = 0; nn < 4; ++nn) {
            float s = s_sh[nn][u];
            as[nn] += s * wsa;
            ar[nn] += s * wsb;
            a1[nn] += s * wu0;
            av0[nn] += v_sh[nn][u * 3 + 0] * wu1;
            av1[nn] += v_sh[nn][u * 3 + 1] * wu1;
            av2[nn] += v_sh[nn][u * 3 + 2] * wu1;
        }
    }
#pragma unroll
    for (int nn = 0; nn < 4; ++nn) {
        int n = n0 + nn;
        g_hps[n * 128 + t] = as[nn];
        g_hpr[n * 128 + t] = ar[nn];
        g_su [n * 128 + t] = a1[nn] * INV_SQRT_MUL;
        g_vup[n * 384 + t * 3 + 0] = av0[nn] * INV_SQRT_MUL;
        g_vup[n * 384 + t * 3 + 1] = av1[nn] * INV_SQRT_MUL;
        g_vup[n * 384 + t * 3 + 2] = av2[nn] * INV_SQRT_MUL;
    }
}

// ---------------------------------------------------------------------------
// Kernel 2: per-edge MLP + message + scatter, f32x2 with edge-pair packing.
// 128 threads, TE=32. cg=t&31 -> cols c0=4cg..c0+3; warp wp=t>>5 owns 8
// edges e0=8wp == 4 pairs p0=4wp. Hidden activations live in ONE smem
// array hT[k][pair] (float2 over an edge pair); h2 overwrites h1 in place
// (barrier-separated). Only 17.4KB smem -> ~116KB L1D left for weights.
// In the GEMM loops the f32x2 packs run over edge pairs: x comes straight
// from smem as a pair, only the (per-column) weight needs a dup.
// ---------------------------------------------------------------------------
__global__ void __launch_bounds__(128, 6) k_edge(
    const float* __restrict__ edge_attrs,
    const float* __restrict__ edge_feats,
    const float* __restrict__ lengths,
    const int*   __restrict__ edge_index,
    const float* __restrict__ W1, const float* __restrict__ b1,
    const float* __restrict__ W2, const float* __restrict__ b2,
    const float* __restrict__ W3)
{
    __shared__ __align__(16) float2 hT[128][17];   // [col k][edge pair], padded

    const int t  = threadIdx.x;
    const int cg = t & 31;
    const int c0 = cg * 4;
    const int wp = t >> 5;
    const int e0 = wp * 8;
    const int p0 = wp * 4;
    const int ebase = blockIdx.x * TE;

    // ---- layer 1 (folded): per pair, compute both edges' 4 cols ----
    {
        float4 bb = *(const float4*)(b1 + c0);
#pragma unroll
        for (int jp = 0; jp < 4; ++jp) {
            float a2[2][4];
#pragma unroll
            for (int h = 0; h < 2; ++h) {
                const int eg  = ebase + e0 + 2 * jp + h;
                const int snd = edge_index[eg];
                const int rcv = edge_index[N_EDGES + eg];
                float4 hs = *(const float4*)(g_hps + snd * 128 + c0);
                float4 hr = *(const float4*)(g_hpr + rcv * 128 + c0);
                float a[4] = { bb.x + hs.x + hr.x, bb.y + hs.y + hr.y,
                               bb.z + hs.z + hr.z, bb.w + hs.w + hr.w };
                float ef[9];
                {
                    float4 q0 = *(const float4*)(edge_feats + eg * 8);
                    float4 q1 = *(const float4*)(edge_feats + eg * 8 + 4);
                    ef[0]=q0.x; ef[1]=q0.y; ef[2]=q0.z; ef[3]=q0.w;
                    ef[4]=q1.x; ef[5]=q1.y; ef[6]=q1.z; ef[7]=q1.w;
                    ef[8]=lengths[eg];
                }
#pragma unroll
                for (int r = 0; r < 9; ++r) {
                    float4 w = *(const float4*)(W1 + (256 + r) * 128 + c0);
                    a[0] += ef[r] * w.x; a[1] += ef[r] * w.y;
                    a[2] += ef[r] * w.z; a[3] += ef[r] * w.w;
                }
                a2[h][0]=silu(a[0]); a2[h][1]=silu(a[1]);
                a2[h][2]=silu(a[2]); a2[h][3]=silu(a[3]);
            }
#pragma unroll
            for (int i = 0; i < 4; ++i)
                hT[c0 + i][p0 + jp] = make_float2(a2[0][i], a2[1][i]);
        }
    }
    __syncthreads();

    // ---- layer 2: 128 -> 128, silu; acc[col][pair] ----
    {
        ull acc[4][4];
        {
            float4 b = *(const float4*)(b2 + c0);
            ull b0 = dup2(b.x), b1d = dup2(b.y), b2d = dup2(b.z), b3 = dup2(b.w);
#pragma unroll
            for (int jp = 0; jp < 4; ++jp) {
                acc[0][jp] = b0; acc[1][jp] = b1d; acc[2][jp] = b2d; acc[3][jp] = b3;
            }
        }
#pragma unroll 2
        for (int k = 0; k < 128; ++k) {
            float4 w = *(const float4*)(W2 + k * 128 + c0);
            ull wd0 = dup2(w.x), wd1 = dup2(w.y), wd2 = dup2(w.z), wd3 = dup2(w.w);
            ull xp0 = *(const ull*)&hT[k][p0 + 0];
            ull xp1 = *(const ull*)&hT[k][p0 + 1];
            ull xp2 = *(const ull*)&hT[k][p0 + 2];
            ull xp3 = *(const ull*)&hT[k][p0 + 3];
            fma2(acc[0][0], wd0, xp0); fma2(acc[0][1], wd0, xp1);
            fma2(acc[0][2], wd0, xp2); fma2(acc[0][3], wd0, xp3);
            fma2(acc[1][0], wd1, xp0); fma2(acc[1][1], wd1, xp1);
            fma2(acc[1][2], wd1, xp2); fma2(acc[1][3], wd1, xp3);
            fma2(acc[2][0], wd2, xp0); fma2(acc[2][1], wd2, xp1);
            fma2(acc[2][2], wd2, xp2); fma2(acc[2][3], wd2, xp3);
            fma2(acc[3][0], wd3, xp0); fma2(acc[3][1], wd3, xp1);
            fma2(acc[3][2], wd3, xp2); fma2(acc[3][3], wd3, xp3);
        }
        __syncthreads();             // all h1 reads complete
#pragma unroll
        for (int i = 0; i < 4; ++i)
#pragma unroll
            for (int jp = 0; jp < 4; ++jp) {
                float2 v = unpack2(acc[i][jp]);
                hT[c0 + i][p0 + jp] = make_float2(silu(v.x), silu(v.y));
            }
    }
    __syncthreads();
    // h2 now lives in hT, read-only below.

    // ======== layer 3: four single-segment sweeps, fused scatter ==========
#pragma unroll 1
    for (int seg = 0; seg < 4; ++seg) {
        ull acc[4][4];
#pragma unroll
        for (int i = 0; i < 4; ++i)
#pragma unroll
            for (int jp = 0; jp < 4; ++jp) acc[i][jp] = 0;

        const float* Wseg = W3 + seg * 128 + c0;
#pragma unroll 2
        for (int k = 0; k < 128; ++k) {
            float4 w = *(const float4*)(Wseg + k * 512);
            ull wd0 = dup2(w.x), wd1 = dup2(w.y), wd2 = dup2(w.z), wd3 = dup2(w.w);
            ull xp0 = *(const ull*)&hT[k][p0 + 0];
            ull xp1 = *(const ull*)&hT[k][p0 + 1];
            ull xp2 = *(const ull*)&hT[k][p0 + 2];
            ull xp3 = *(const ull*)&hT[k][p0 + 3];
            fma2(acc[0][0], wd0, xp0); fma2(acc[0][1], wd0, xp1);
            fma2(acc[0][2], wd0, xp2); fma2(acc[0][3], wd0, xp3);
            fma2(acc[1][0], wd1, xp0); fma2(acc[1][1], wd1, xp1);
            fma2(acc[1][2], wd1, xp2); fma2(acc[1][3], wd1, xp3);
            fma2(acc[2][0], wd2, xp0); fma2(acc[2][1], wd2, xp1);
            fma2(acc[2][2], wd2, xp2); fma2(acc[2][3], wd2, xp3);
            fma2(acc[3][0], wd3, xp0); fma2(acc[3][1], wd3, xp1);
            fma2(acc[3][2], wd3, xp2); fma2(acc[3][3], wd3, xp3);
        }

        // ---- fused scatter for this segment ----
#pragma unroll
        for (int jp = 0; jp < 4; ++jp) {
            float2 vc0 = unpack2(acc[0][jp]);
            float2 vc1 = unpack2(acc[1][jp]);
            float2 vc2 = unpack2(acc[2][jp]);
            float2 vc3 = unpack2(acc[3][jp]);
#pragma unroll
            for (int h = 0; h < 2; ++h) {
                const int eg  = ebase + e0 + 2 * jp + h;
                const int snd = edge_index[eg];
                const int rcv = edge_index[N_EDGES + eg];
                float4 ea = *(const float4*)(edge_attrs + eg * 4);
                const float av[4] = { h ? vc0.y : vc0.x, h ? vc1.y : vc1.x,
                                      h ? vc2.y : vc2.x, h ? vc3.y : vc3.x };
                float* base = g_msg + rcv * 1024;

                if (seg == 0) {          // m0a = w0*se*y0 -> [0,128)
                    float4 sev = *(const float4*)(g_su + snd * 128 + c0);
                    red_add_v4(base + c0,
                               av[0]*sev.x*ea.x, av[1]*sev.y*ea.x,
                               av[2]*sev.z*ea.x, av[3]*sev.w*ea.x);
                } else if (seg == 1) {   // m1a = (w1*se) (x) y1 -> [256,640)
                    float4 sev = *(const float4*)(g_su + snd * 128 + c0);
                    const float se[4] = {sev.x, sev.y, sev.z, sev.w};
                    float o[12];
#pragma unroll
                    for (int m = 0; m < 4; ++m) {
                        float t1 = av[m] * se[m];
                        o[3*m+0] = t1 * ea.y; o[3*m+1] = t1 * ea.z; o[3*m+2] = t1 * ea.w;
                    }
                    float* p = base + 256 + c0 * 3;
                    red_add_v4(p,     o[0], o[1], o[2],  o[3]);
                    red_add_v4(p + 4, o[4], o[5], o[6],  o[7]);
                    red_add_v4(p + 8, o[8], o[9], o[10], o[11]);
                } else if (seg == 2) {   // m1b = (w2*y0) * ve -> [640,1024)
                    const float4* pv = (const float4*)(g_vup + snd * 384 + c0 * 3);
                    float4 v0 = pv[0], v1 = pv[1], v2 = pv[2];
                    float o[12];
                    o[0]  = av[0]*ea.x*v0.x; o[1]  = av[0]*ea.x*v0.y; o[2]  = av[0]*ea.x*v0.z;
                    o[3]  = av[1]*ea.x*v0.w; o[4]  = av[1]*ea.x*v1.x; o[5]  = av[1]*ea.x*v1.y;
                    o[6]  = av[2]*ea.x*v1.z; o[7]  = av[2]*ea.x*v1.w; o[8]  = av[2]*ea.x*v2.x;
                    o[9]  = av[3]*ea.x*v2.y; o[10] = av[3]*ea.x*v2.z; o[11] = av[3]*ea.x*v2.w;
                    float* p = base + 640 + c0 * 3;
                    red_add_v4(p,     o[0], o[1], o[2],  o[3]);
                    red_add_v4(p + 4, o[4], o[5], o[6],  o[7]);
                    red_add_v4(p + 8, o[8], o[9], o[10], o[11]);
                } else {                 // m0b = w3*(ve.y1)*inv_sqrt3 -> [128,256)
                    const float4* pv = (const float4*)(g_vup + snd * 384 + c0 * 3);
                    float4 v0 = pv[0], v1 = pv[1], v2 = pv[2];
                    float d0 = v0.x*ea.y + v0.y*ea.z + v0.z*ea.w;
                    float d1 = v0.w*ea.y + v1.x*ea.z + v1.y*ea.w;
                    float d2 = v1.z*ea.y + v1.w*ea.z + v2.x*ea.w;
                    float d3 = v2.y*ea.y + v2.z*ea.z + v2.w*ea.w;
                    red_add_v4(base + 128 + c0,
                               av[0]*d0*INV_SQRT3, av[1]*d1*INV_SQRT3,
                               av[2]*d2*INV_SQRT3, av[3]*d3*INV_SQRT3);
                }
            }
        }
    }
}

// ---------------------------------------------------------------------------
// Kernel 3: node output. 8 nodes per block, 256 threads.
// ---------------------------------------------------------------------------
__global__ void __launch_bounds__(256) k_out(
    const float* __restrict__ W0,
    const float* __restrict__ W1o,
    float* __restrict__ out)
{
    __shared__ __align__(16) float m_sm[8 * 1024];
    const int n0 = blockIdx.x * 8;
    const int t  = threadIdx.x;
    const int tc = t & 127;
    const int nb = (t >> 7) * 4;      // node group base: 0 or 4

    {
        const float4* src = (const float4*)(g_msg + n0 * 1024);
        float4* dst = (float4*)m_sm;
#pragma unroll
        for (int i = 0; i < 8; ++i) dst[t + 256 * i] = src[t + 256 * i];
    }
    __syncthreads();

    float a0[4], v0[4], v1[4], v2[4];
#pragma unroll
    for (int nn = 0; nn < 4; ++nn) { a0[nn]=0.f; v0[nn]=0.f; v1[nn]=0.f; v2[nn]=0.f; }

    for (int u = 0; u < 256; u += 4) {
        float w0[4], w1[4];
#pragma unroll
        for (int i = 0; i < 4; ++i) {
            w0[i] = W0 [(u + i) * 128 + tc];
            w1[i] = W1o[(u + i) * 128 + tc];
        }
#pragma unroll
        for (int nn = 0; nn < 4; ++nn) {
            const float* row = m_sm + (nb + nn) * 1024;
            float4 ms = *(const float4*)&row[u];
            a0[nn] += ms.x * w0[0] + ms.y * w0[1] + ms.z * w0[2] + ms.w * w0[3];
            float4 va = *(const float4*)&row[256 + u * 3];
            float4 vb = *(const float4*)&row[256 + u * 3 + 4];
            float4 vc = *(const float4*)&row[256 + u * 3 + 8];
            v0[nn] += va.x * w1[0] + va.w * w1[1] + vb.z * w1[2] + vc.y * w1[3];
            v1[nn] += va.y * w1[0] + vb.x * w1[1] + vb.w * w1[2] + vc.z * w1[3];
            v2[nn] += va.z * w1[0] + vb.y * w1[1] + vc.x * w1[2] + vc.w * w1[3];
        }
    }

#pragma unroll
    for (int nn = 0; nn < 4; ++nn) {
        *(float4*)(out + (n0 + nb + nn) * 512 + tc * 4) =
            make_float4(a0[nn] * OUT_SCALE, v0[nn] * OUT_SCALE,
                        v1[nn] * OUT_SCALE, v2[nn] * OUT_SCALE);
    }
}

// ---------------------------------------------------------------------------
// Launch
// ---------------------------------------------------------------------------
extern "C" void kernel_launch(void* const* d_in, const int* in_sizes, int n_in,
                              void* d_out, int out_size)
{
    const float* node_feats = (const float*)d_in[0];
    const float* edge_attrs = (const float*)d_in[1];
    const float* edge_feats = (const float*)d_in[2];
    const float* lengths    = (const float*)d_in[3];
    const int*   edge_index = (const int*)  d_in[4];
    const float* W_scalar   = (const float*)d_in[5];
    const float* W_up0      = (const float*)d_in[6];
    const float* W_up1      = (const float*)d_in[7];
    const float* W_mlp1     = (const float*)d_in[8];
    const float* b_mlp1     = (const float*)d_in[9];
    const float* W_mlp2     = (const float*)d_in[10];
    const float* b_mlp2     = (const float*)d_in[11];
    const float* W_mlp3     = (const float*)d_in[12];
    const float* W_out0     = (const float*)d_in[13];
    const float* W_out1     = (const float*)d_in[14];
    float* out = (float*)d_out;

    k_zero<<<5000, 512>>>();
    k_w<<<dim3(128, 2), 128>>>(W_scalar, W_mlp1);
    k_node<<<N_NODES / 4, 128>>>(node_feats, W_up0, W_up1);
    k_edge<<<N_EDGES / TE, 128>>>(edge_attrs, edge_feats, lengths, edge_index,
                                  W_mlp1, b_mlp1, W_mlp2, b_mlp2, W_mlp3);
    k_out<<<N_NODES / 8, 256>>>(W_out0, W_out1, out);
}

// round 9
// speedup vs baseline: 1.2665x; 1.0525x over previous
#include <cuda_runtime.h>

#define N_NODES 10000
#define N_EDGES 160000
#define TE 32                    // edges per block in the edge kernel

#define INV_SQRT_MUL 0.08838834764831845f   // 1/sqrt(128)
#define INV_SQRT3    0.57735026918962576f
#define OUT_SCALE    0.00390625f            // (1/sqrt(256)) / 16

typedef unsigned long long ull;

// ---------------------------------------------------------------------------
// Scratch (device globals: allocation-free)
// ---------------------------------------------------------------------------
__device__ float g_hps[N_NODES * 128];   // s_in @ (inv * W_scalar @ W1[0:128])
__device__ float g_hpr[N_NODES * 128];   // s_in @ (inv * W_scalar @ W1[128:256])
__device__ float g_su [N_NODES * 128];   // s_up
__device__ float g_vup[N_NODES * 384];   // v_up, layout [n][w][i] (i fastest)
__device__ float g_msg[N_NODES * 1024];  // segment-sum accumulator
__device__ float g_Wsa[128 * 128];       // inv * W_scalar @ W1[0:128]
__device__ float g_Wsb[128 * 128];       // inv * W_scalar @ W1[128:256]

static __device__ __forceinline__ float silu(float x) {
    return x / (1.0f + __expf(-x));
}

static __device__ __forceinline__ void red_add_v4(float* addr, float a, float b,
                                                  float c, float d) {
    asm volatile("red.global.add.v4.f32 [%0], {%1, %2, %3, %4};"
                 :: "l"(addr), "f"(a), "f"(b), "f"(c), "f"(d) : "memory");
}

// ---- packed f32x2 helpers --------------------------------------------------
static __device__ __forceinline__ ull dup2(float x) {
    ull r; asm("mov.b64 %0, {%1, %1};" : "=l"(r) : "f"(x)); return r;
}
static __device__ __forceinline__ void fma2(ull& acc, ull a, ull b) {
    asm("fma.rn.f32x2 %0, %1, %2, %0;" : "+l"(acc) : "l"(a), "l"(b));
}
static __device__ __forceinline__ float2 unpack2(ull p) {
    float2 f; asm("mov.b64 {%0, %1}, %2;" : "=f"(f.x), "=f"(f.y) : "l"(p)); return f;
}

// ---------------------------------------------------------------------------
// Kernel 0: zero the message accumulator
// ---------------------------------------------------------------------------
__global__ void k_zero() {
    int i = blockIdx.x * blockDim.x + threadIdx.x;
    ((float4*)g_msg)[i] = make_float4(0.f, 0.f, 0.f, 0.f);
}

// ---------------------------------------------------------------------------
// Kernel W: fold W_scalar into the first MLP layer.
// ---------------------------------------------------------------------------
__global__ void __launch_bounds__(128) k_w(
    const float* __restrict__ Ws, const float* __restrict__ W1)
{
    __shared__ float row[128];
    const int u = blockIdx.x, t = threadIdx.x;
    row[t] = Ws[u * 128 + t];
    __syncthreads();
    const float* W1p = W1 + (blockIdx.y ? 128 * 128 : 0);
    float a = 0.f;
#pragma unroll 4
    for (int c = 0; c < 128; ++c) a += row[c] * W1p[c * 128 + t];
    (blockIdx.y ? g_Wsb : g_Wsa)[u * 128 + t] = a * INV_SQRT_MUL;
}

// ---------------------------------------------------------------------------
// Kernel 1: per-node precompute, 4 nodes per block.
// ---------------------------------------------------------------------------
__global__ void __launch_bounds__(128) k_node(
    const float* __restrict__ nf,
    const float* __restrict__ Wu0,
    const float* __restrict__ Wu1)
{
    __shared__ float s_sh[4][128];
    __shared__ float v_sh[4][384];
    const int n0 = blockIdx.x * 4;
    const int t = threadIdx.x;

#pragma unroll
    for (int nn = 0; nn < 4; ++nn) {
        const float* src = nf + (n0 + nn) * 512;
        s_sh[nn][t]       = src[t];
        v_sh[nn][t]       = src[128 + t];
        v_sh[nn][t + 128] = src[256 + t];
        v_sh[nn][t + 256] = src[384 + t];
    }
    __syncthreads();

    float as[4], ar[4], a1[4], av0[4], av1[4], av2[4];
#pragma unroll
    for (int nn = 0; nn < 4; ++nn) {
        as[nn]=0.f; ar[nn]=0.f; a1[nn]=0.f; av0[nn]=0.f; av1[nn]=0.f; av2[nn]=0.f;
    }

#pragma unroll 2
    for (int u = 0; u < 128; ++u) {
        float wsa = g_Wsa[u * 128 + t];
        float wsb = g_Wsb[u * 128 + t];
        float wu0 = Wu0[u * 128 + t];
        float wu1 = Wu1[u * 128 + t];
#pragma unroll
        for (int nn = 0; nn < 4; ++nn) {
            float s = s_sh[nn][u];
            as[nn] += s * wsa;
            ar[nn] += s * wsb;
            a1[nn] += s * wu0;
            av0[nn] += v_sh[nn][u * 3 + 0] * wu1;
            av1[nn] += v_sh[nn][u * 3 + 1] * wu1;
            av2[nn] += v_sh[nn][u * 3 + 2] * wu1;
        }
    }
#pragma unroll
    for (int nn = 0; nn < 4; ++nn) {
        int n = n0 + nn;
        g_hps[n * 128 + t] = as[nn];
        g_hpr[n * 128 + t] = ar[nn];
        g_su [n * 128 + t] = a1[nn] * INV_SQRT_MUL;
        g_vup[n * 384 + t * 3 + 0] = av0[nn] * INV_SQRT_MUL;
        g_vup[n * 384 + t * 3 + 1] = av1[nn] * INV_SQRT_MUL;
        g_vup[n * 384 + t * 3 + 2] = av2[nn] * INV_SQRT_MUL;
    }
}

// ---------------------------------------------------------------------------
// Kernel 2: per-edge MLP + message + scatter, f32x2 edge-pair packing.
// 128 threads, TE=32, 8 blocks/SM. cg=t&31 -> cols c0=4cg..c0+3; warp
// wp=t>>5 owns 8 edges (4 pairs). hT[k][pair] float2 rows padded to 18
// (144B, 16B-aligned at even pair index) so pair reads are 2x LDS.128.
// Edge indices cached in smem once; h2 overwrites h1 in place.
// ---------------------------------------------------------------------------
__global__ void __launch_bounds__(128, 8) k_edge(
    const float* __restrict__ edge_attrs,
    const float* __restrict__ edge_feats,
    const float* __restrict__ lengths,
    const int*   __restrict__ edge_index,
    const float* __restrict__ W1, const float* __restrict__ b1,
    const float* __restrict__ W2, const float* __restrict__ b2,
    const float* __restrict__ W3)
{
    __shared__ __align__(16) float2 hT[128][18];   // [col k][edge pair], 144B rows
    __shared__ int s_idx[2][TE];                   // [0]=snd, [1]=rcv

    const int t  = threadIdx.x;
    const int cg = t & 31;
    const int c0 = cg * 4;
    const int wp = t >> 5;
    const int e0 = wp * 8;
    const int p0 = wp * 4;
    const int ebase = blockIdx.x * TE;

    if (t < 64) {
        const int e = t & 31;
        const int r = t >> 5;
        s_idx[r][e] = edge_index[r * N_EDGES + ebase + e];
    }
    __syncthreads();

    // ---- layer 1 (folded): per pair, compute both edges' 4 cols ----
    {
        float4 bb = *(const float4*)(b1 + c0);
#pragma unroll
        for (int jp = 0; jp < 4; ++jp) {
            float a2[2][4];
#pragma unroll
            for (int h = 0; h < 2; ++h) {
                const int el  = e0 + 2 * jp + h;
                const int eg  = ebase + el;
                const int snd = s_idx[0][el];
                const int rcv = s_idx[1][el];
                float4 hs = *(const float4*)(g_hps + snd * 128 + c0);
                float4 hr = *(const float4*)(g_hpr + rcv * 128 + c0);
                float a[4] = { bb.x + hs.x + hr.x, bb.y + hs.y + hr.y,
                               bb.z + hs.z + hr.z, bb.w + hs.w + hr.w };
                float ef[9];
                {
                    float4 q0 = *(const float4*)(edge_feats + eg * 8);
                    float4 q1 = *(const float4*)(edge_feats + eg * 8 + 4);
                    ef[0]=q0.x; ef[1]=q0.y; ef[2]=q0.z; ef[3]=q0.w;
                    ef[4]=q1.x; ef[5]=q1.y; ef[6]=q1.z; ef[7]=q1.w;
                    ef[8]=lengths[eg];
                }
#pragma unroll
                for (int r = 0; r < 9; ++r) {
                    float4 w = *(const float4*)(W1 + (256 + r) * 128 + c0);
                    a[0] += ef[r] * w.x; a[1] += ef[r] * w.y;
                    a[2] += ef[r] * w.z; a[3] += ef[r] * w.w;
                }
                a2[h][0]=silu(a[0]); a2[h][1]=silu(a[1]);
                a2[h][2]=silu(a[2]); a2[h][3]=silu(a[3]);
            }
#pragma unroll
            for (int i = 0; i < 4; ++i)
                hT[c0 + i][p0 + jp] = make_float2(a2[0][i], a2[1][i]);
        }
    }
    __syncthreads();

    // ---- layer 2: 128 -> 128, silu; acc[col][pair] ----
    {
        ull acc[4][4];
        {
            float4 b = *(const float4*)(b2 + c0);
            ull b0 = dup2(b.x), b1d = dup2(b.y), b2d = dup2(b.z), b3 = dup2(b.w);
#pragma unroll
            for (int jp = 0; jp < 4; ++jp) {
                acc[0][jp] = b0; acc[1][jp] = b1d; acc[2][jp] = b2d; acc[3][jp] = b3;
            }
        }
#pragma unroll 2
        for (int k = 0; k < 128; ++k) {
            float4 w = *(const float4*)(W2 + k * 128 + c0);
            ull wd0 = dup2(w.x), wd1 = dup2(w.y), wd2 = dup2(w.z), wd3 = dup2(w.w);
            ulonglong2 xa = *(const ulonglong2*)&hT[k][p0];
            ulonglong2 xb = *(const ulonglong2*)&hT[k][p0 + 2];
            fma2(acc[0][0], wd0, xa.x); fma2(acc[0][1], wd0, xa.y);
            fma2(acc[0][2], wd0, xb.x); fma2(acc[0][3], wd0, xb.y);
            fma2(acc[1][0], wd1, xa.x); fma2(acc[1][1], wd1, xa.y);
            fma2(acc[1][2], wd1, xb.x); fma2(acc[1][3], wd1, xb.y);
            fma2(acc[2][0], wd2, xa.x); fma2(acc[2][1], wd2, xa.y);
            fma2(acc[2][2], wd2, xb.x); fma2(acc[2][3], wd2, xb.y);
            fma2(acc[3][0], wd3, xa.x); fma2(acc[3][1], wd3, xa.y);
            fma2(acc[3][2], wd3, xb.x); fma2(acc[3][3], wd3, xb.y);
        }
        __syncthreads();             // all h1 reads complete
#pragma unroll
        for (int i = 0; i < 4; ++i)
#pragma unroll
            for (int jp = 0; jp < 4; ++jp) {
                float2 v = unpack2(acc[i][jp]);
                hT[c0 + i][p0 + jp] = make_float2(silu(v.x), silu(v.y));
            }
    }
    __syncthreads();
    // h2 now lives in hT, read-only below.

    // ======== layer 3: four single-segment sweeps, fused scatter ==========
#pragma unroll 1
    for (int seg = 0; seg < 4; ++seg) {
        ull acc[4][4];
#pragma unroll
        for (int i = 0; i < 4; ++i)
#pragma unroll
            for (int jp = 0; jp < 4; ++jp) acc[i][jp] = 0;

        const float* Wseg = W3 + seg * 128 + c0;
#pragma unroll 2
        for (int k = 0; k < 128; ++k) {
            float4 w = *(const float4*)(Wseg + k * 512);
            ull wd0 = dup2(w.x), wd1 = dup2(w.y), wd2 = dup2(w.z), wd3 = dup2(w.w);
            ulonglong2 xa = *(const ulonglong2*)&hT[k][p0];
            ulonglong2 xb = *(const ulonglong2*)&hT[k][p0 + 2];
            fma2(acc[0][0], wd0, xa.x); fma2(acc[0][1], wd0, xa.y);
            fma2(acc[0][2], wd0, xb.x); fma2(acc[0][3], wd0, xb.y);
            fma2(acc[1][0], wd1, xa.x); fma2(acc[1][1], wd1, xa.y);
            fma2(acc[1][2], wd1, xb.x); fma2(acc[1][3], wd1, xb.y);
            fma2(acc[2][0], wd2, xa.x); fma2(acc[2][1], wd2, xa.y);
            fma2(acc[2][2], wd2, xb.x); fma2(acc[2][3], wd2, xb.y);
            fma2(acc[3][0], wd3, xa.x); fma2(acc[3][1], wd3, xa.y);
            fma2(acc[3][2], wd3, xb.x); fma2(acc[3][3], wd3, xb.y);
        }

        // ---- fused scatter for this segment ----
#pragma unroll
        for (int jp = 0; jp < 4; ++jp) {
            float2 vc0 = unpack2(acc[0][jp]);
            float2 vc1 = unpack2(acc[1][jp]);
            float2 vc2 = unpack2(acc[2][jp]);
            float2 vc3 = unpack2(acc[3][jp]);
#pragma unroll
            for (int h = 0; h < 2; ++h) {
                const int el  = e0 + 2 * jp + h;
                const int eg  = ebase + el;
                const int snd = s_idx[0][el];
                const int rcv = s_idx[1][el];
                float4 ea = *(const float4*)(edge_attrs + eg * 4);
                const float av[4] = { h ? vc0.y : vc0.x, h ? vc1.y : vc1.x,
                                      h ? vc2.y : vc2.x, h ? vc3.y : vc3.x };
                float* base = g_msg + rcv * 1024;

                if (seg == 0) {          // m0a = w0*se*y0 -> [0,128)
                    float4 sev = *(const float4*)(g_su + snd * 128 + c0);
                    red_add_v4(base + c0,
                               av[0]*sev.x*ea.x, av[1]*sev.y*ea.x,
                               av[2]*sev.z*ea.x, av[3]*sev.w*ea.x);
                } else if (seg == 1) {   // m1a = (w1*se) (x) y1 -> [256,640)
                    float4 sev = *(const float4*)(g_su + snd * 128 + c0);
                    const float se[4] = {sev.x, sev.y, sev.z, sev.w};
                    float o[12];
#pragma unroll
                    for (int m = 0; m < 4; ++m) {
                        float t1 = av[m] * se[m];
                        o[3*m+0] = t1 * ea.y; o[3*m+1] = t1 * ea.z; o[3*m+2] = t1 * ea.w;
                    }
                    float* p = base + 256 + c0 * 3;
                    red_add_v4(p,     o[0], o[1], o[2],  o[3]);
                    red_add_v4(p + 4, o[4], o[5], o[6],  o[7]);
                    red_add_v4(p + 8, o[8], o[9], o[10], o[11]);
                } else if (seg == 2) {   // m1b = (w2*y0) * ve -> [640,1024)
                    const float4* pv = (const float4*)(g_vup + snd * 384 + c0 * 3);
                    float4 v0 = pv[0], v1 = pv[1], v2 = pv[2];
                    float o[12];
                    o[0]  = av[0]*ea.x*v0.x; o[1]  = av[0]*ea.x*v0.y; o[2]  = av[0]*ea.x*v0.z;
                    o[3]  = av[1]*ea.x*v0.w; o[4]  = av[1]*ea.x*v1.x; o[5]  = av[1]*ea.x*v1.y;
                    o[6]  = av[2]*ea.x*v1.z; o[7]  = av[2]*ea.x*v1.w; o[8]  = av[2]*ea.x*v2.x;
                    o[9]  = av[3]*ea.x*v2.y; o[10] = av[3]*ea.x*v2.z; o[11] = av[3]*ea.x*v2.w;
                    float* p = base + 640 + c0 * 3;
                    red_add_v4(p,     o[0], o[1], o[2],  o[3]);
                    red_add_v4(p + 4, o[4], o[5], o[6],  o[7]);
                    red_add_v4(p + 8, o[8], o[9], o[10], o[11]);
                } else {                 // m0b = w3*(ve.y1)*inv_sqrt3 -> [128,256)
                    const float4* pv = (const float4*)(g_vup + snd * 384 + c0 * 3);
                    float4 v0 = pv[0], v1 = pv[1], v2 = pv[2];
                    float d0 = v0.x*ea.y + v0.y*ea.z + v0.z*ea.w;
                    float d1 = v0.w*ea.y + v1.x*ea.z + v1.y*ea.w;
                    float d2 = v1.z*ea.y + v1.w*ea.z + v2.x*ea.w;
                    float d3 = v2.y*ea.y + v2.z*ea.z + v2.w*ea.w;
                    red_add_v4(base + 128 + c0,
                               av[0]*d0*INV_SQRT3, av[1]*d1*INV_SQRT3,
                               av[2]*d2*INV_SQRT3, av[3]*d3*INV_SQRT3);
                }
            }
        }
    }
}

// ---------------------------------------------------------------------------
// Kernel 3: node output. 8 nodes per block, 256 threads.
// ---------------------------------------------------------------------------
__global__ void __launch_bounds__(256) k_out(
    const float* __restrict__ W0,
    const float* __restrict__ W1o,
    float* __restrict__ out)
{
    __shared__ __align__(16) float m_sm[8 * 1024];
    const int n0 = blockIdx.x * 8;
    const int t  = threadIdx.x;
    const int tc = t & 127;
    const int nb = (t >> 7) * 4;      // node group base: 0 or 4

    {
        const float4* src = (const float4*)(g_msg + n0 * 1024);
        float4* dst = (float4*)m_sm;
#pragma unroll
        for (int i = 0; i < 8; ++i) dst[t + 256 * i] = src[t + 256 * i];
    }
    __syncthreads();

    float a0[4], v0[4], v1[4], v2[4];
#pragma unroll
    for (int nn = 0; nn < 4; ++nn) { a0[nn]=0.f; v0[nn]=0.f; v1[nn]=0.f; v2[nn]=0.f; }

    for (int u = 0; u < 256; u += 4) {
        float w0[4], w1[4];
#pragma unroll
        for (int i = 0; i < 4; ++i) {
            w0[i] = W0 [(u + i) * 128 + tc];
            w1[i] = W1o[(u + i) * 128 + tc];
        }
#pragma unroll
        for (int nn = 0; nn < 4; ++nn) {
            const float* row = m_sm + (nb + nn) * 1024;
            float4 ms = *(const float4*)&row[u];
            a0[nn] += ms.x * w0[0] + ms.y * w0[1] + ms.z * w0[2] + ms.w * w0[3];
            float4 va = *(const float4*)&row[256 + u * 3];
            float4 vb = *(const float4*)&row[256 + u * 3 + 4];
            float4 vc = *(const float4*)&row[256 + u * 3 + 8];
            v0[nn] += va.x * w1[0] + va.w * w1[1] + vb.z * w1[2] + vc.y * w1[3];
            v1[nn] += va.y * w1[0] + vb.x * w1[1] + vb.w * w1[2] + vc.z * w1[3];
            v2[nn] += va.z * w1[0] + vb.y * w1[1] + vc.x * w1[2] + vc.w * w1[3];
        }
    }

#pragma unroll
    for (int nn = 0; nn < 4; ++nn) {
        *(float4*)(out + (n0 + nb + nn) * 512 + tc * 4) =
            make_float4(a0[nn] * OUT_SCALE, v0[nn] * OUT_SCALE,
                        v1[nn] * OUT_SCALE, v2[nn] * OUT_SCALE);
    }
}

// ---------------------------------------------------------------------------
// Launch
// ---------------------------------------------------------------------------
extern "C" void kernel_launch(void* const* d_in, const int* in_sizes, int n_in,
                              void* d_out, int out_size)
{
    const float* node_feats = (const float*)d_in[0];
    const float* edge_attrs = (const float*)d_in[1];
    const float* edge_feats = (const float*)d_in[2];
    const float* lengths    = (const float*)d_in[3];
    const int*   edge_index = (const int*)  d_in[4];
    const float* W_scalar   = (const float*)d_in[5];
    const float* W_up0      = (const float*)d_in[6];
    const float* W_up1      = (const float*)d_in[7];
    const float* W_mlp1     = (const float*)d_in[8];
    const float* b_mlp1     = (const float*)d_in[9];
    const float* W_mlp2     = (const float*)d_in[10];
    const float* b_mlp2     = (const float*)d_in[11];
    const float* W_mlp3     = (const float*)d_in[12];
    const float* W_out0     = (const float*)d_in[13];
    const float* W_out1     = (const float*)d_in[14];
    float* out = (float*)d_out;

    k_zero<<<5000, 512>>>();
    k_w<<<dim3(128, 2), 128>>>(W_scalar, W_mlp1);
    k_node<<<N_NODES / 4, 128>>>(node_feats, W_up0, W_up1);
    k_edge<<<N_EDGES / TE, 128>>>(edge_attrs, edge_feats, lengths, edge_index,
                                  W_mlp1, b_mlp1, W_mlp2, b_mlp2, W_mlp3);
    k_out<<<N_NODES / 8, 256>>>(W_out0, W_out1, out);
}